// round 4
// baseline (speedup 1.0000x reference)
#include <cuda_runtime.h>
#include <cuda_bf16.h>

// Fused single-head causal attention, one CTA per batch element.
// Round 3: fixed transposed-tile stride (QS=68 >= 64), split weight residency
// (Wq+Wk then Wv in a 4608-float union region also reused for sWei)
// -> peak smem 69632B -> 3 CTAs/SM. Vectorized LDS in score/AV phases.

#define T_DIM 64
#define C_DIM 48
#define H_DIM 48

#define XS 49    // sX / sV row stride (row-major [64][49])
#define QS 68    // sQt / sKt row stride (transposed [48][68]: 64 cols + pad, 16B-aligned)
#define WS 68    // sWei row stride ([64][68], 16B-aligned)

// smem layout (floats):
//   [0, 4608)      union: phase1a Wq[0,2304)+Wk[2304,4608) ; phase1b Wv[0,2304) ;
//                  phase2+ sWei [64][68]=4352
//   [4608, 7744)   sX  [64][49] = 3136
//   [7744, 11008)  sQt [48][68] = 3264  (transposed, 16B-aligned base+rows)
//   [11008,14272)  sKt [48][68] = 3264
//   [14272,17408)  sV  [64][49] = 3136
// total = 17408 floats = 69632 bytes -> 3 CTAs/SM
#define SMEM_FLOATS 17408

__global__ __launch_bounds__(256, 3) void head_attn_kernel(
    const float* __restrict__ x,
    const float* __restrict__ Wq,
    const float* __restrict__ Wk,
    const float* __restrict__ Wv,
    float* __restrict__ out)
{
    extern __shared__ float smem[];
    float* sU   = smem;             // union region: weights / sWei
    float* sWei = smem;             // [64][WS] (phase 2+)
    float* sX   = smem + 4608;      // [64][XS]
    float* sQt  = smem + 7744;      // [48][QS] transposed
    float* sKt  = smem + 11008;     // [48][QS] transposed
    float* sV   = smem + 14272;     // [64][XS]

    const int tid = threadIdx.x;
    const long long b = blockIdx.x;

    // ---- Load Wq, Wk (float4) + x[b] ----
    {
        const float4* wq4 = (const float4*)Wq;
        const float4* wk4 = (const float4*)Wk;
        #pragma unroll 1
        for (int i = tid; i < 2 * 576; i += 256) {
            int m = i / 576;
            int j = i - m * 576;
            ((float4*)(sU + m * 2304))[j] = (m == 0) ? wq4[j] : wk4[j];
        }
        const float* xsrc = x + b * (T_DIM * C_DIM);
        #pragma unroll 1
        for (int i = tid; i < T_DIM * C_DIM; i += 256) {
            int r = i / C_DIM;
            int c = i - r * C_DIM;
            sX[r * XS + c] = xsrc[i];
        }
    }
    __syncthreads();

    const int tTile = tid >> 4;       // 0..15
    const int lo    = tid & 15;       // 0..15
    const int t0 = tTile * 4;         // 4 t-rows per thread
    const int h0 = lo * 3;            // 3 head-cols per thread (proj & output)
    const int s0 = lo * 4;            // 4 score-cols per thread

    // ---- Phase 1a: Q,K projections (4 rows x 3 cols x 2 matrices per thread).
    //      Stored TRANSPOSED [h][t].
    {
        float acc[2][12];
        #pragma unroll
        for (int m = 0; m < 2; ++m)
            #pragma unroll
            for (int j = 0; j < 12; ++j) acc[m][j] = 0.0f;

        #pragma unroll 2
        for (int c = 0; c < C_DIM; ++c) {
            float xv[4];
            #pragma unroll
            for (int i = 0; i < 4; ++i) xv[i] = sX[(t0 + i) * XS + c];  // broadcast in lo
            #pragma unroll
            for (int m = 0; m < 2; ++m) {
                #pragma unroll
                for (int j = 0; j < 3; ++j) {
                    float wv = sU[m * 2304 + c * 48 + h0 + j];
                    #pragma unroll
                    for (int i = 0; i < 4; ++i)
                        acc[m][i * 3 + j] += xv[i] * wv;
                }
            }
        }
        #pragma unroll
        for (int i = 0; i < 4; ++i) {
            #pragma unroll
            for (int j = 0; j < 3; ++j) {
                sQt[(h0 + j) * QS + (t0 + i)] = acc[0][i * 3 + j];
                sKt[(h0 + j) * QS + (t0 + i)] = acc[1][i * 3 + j];
            }
        }
    }
    __syncthreads();

    // ---- Load Wv into union region (Wq/Wk dead) ----
    {
        const float4* wv4 = (const float4*)Wv;
        #pragma unroll 1
        for (int j = tid; j < 576; j += 256)
            ((float4*)sU)[j] = wv4[j];
    }
    __syncthreads();

    // ---- Phase 1b: V projection (4 rows x 3 cols), stored row-major [t][h] ----
    {
        float accv[12];
        #pragma unroll
        for (int j = 0; j < 12; ++j) accv[j] = 0.0f;

        #pragma unroll 2
        for (int c = 0; c < C_DIM; ++c) {
            float xv[4];
            #pragma unroll
            for (int i = 0; i < 4; ++i) xv[i] = sX[(t0 + i) * XS + c];
            #pragma unroll
            for (int j = 0; j < 3; ++j) {
                float wv = sU[c * 48 + h0 + j];
                #pragma unroll
                for (int i = 0; i < 4; ++i)
                    accv[i * 3 + j] += xv[i] * wv;
            }
        }
        #pragma unroll
        for (int i = 0; i < 4; ++i)
            #pragma unroll
            for (int j = 0; j < 3; ++j)
                sV[(t0 + i) * XS + (h0 + j)] = accv[i * 3 + j];
    }
    __syncthreads();

    // ---- Phase 2: scores = Q K^T * scale, causal-masked. 4x4 tile per thread.
    //      Per h: 1 LDS.128 (Q broadcast) + 1 LDS.128 (K contiguous) + 16 FMA.
    //      Writes sWei over the union region (Wv dead).
    {
        float sc[16];
        #pragma unroll
        for (int j = 0; j < 16; ++j) sc[j] = 0.0f;

        #pragma unroll 4
        for (int h = 0; h < H_DIM; ++h) {
            float4 q4 = *(const float4*)&sQt[h * QS + t0];
            float4 k4 = *(const float4*)&sKt[h * QS + s0];
            float qv[4] = {q4.x, q4.y, q4.z, q4.w};
            float kv[4] = {k4.x, k4.y, k4.z, k4.w};
            #pragma unroll
            for (int i = 0; i < 4; ++i)
                #pragma unroll
                for (int j = 0; j < 4; ++j)
                    sc[i * 4 + j] += qv[i] * kv[j];
        }
        const float scale = 0.144337567297406441f; // 1/sqrt(48)
        #pragma unroll
        for (int i = 0; i < 4; ++i) {
            int t = t0 + i;
            float4 w4;
            w4.x = (s0 + 0 <= t) ? sc[i * 4 + 0] * scale : -1e30f;
            w4.y = (s0 + 1 <= t) ? sc[i * 4 + 1] * scale : -1e30f;
            w4.z = (s0 + 2 <= t) ? sc[i * 4 + 2] * scale : -1e30f;
            w4.w = (s0 + 3 <= t) ? sc[i * 4 + 3] * scale : -1e30f;
            *(float4*)&sWei[t * WS + s0] = w4;   // STS.128, conflict-free
        }
    }
    __syncthreads();

    // ---- Phase 3: row softmax. 8 warps x 8 rows; 2 elements per lane ----
    {
        const int warp = tid >> 5;
        const int lane = tid & 31;
        #pragma unroll 1
        for (int r8 = 0; r8 < 8; ++r8) {
            int r = warp * 8 + r8;
            float v0 = sWei[r * WS + lane];
            float v1 = sWei[r * WS + lane + 32];
            float mx = fmaxf(v0, v1);
            #pragma unroll
            for (int off = 16; off > 0; off >>= 1)
                mx = fmaxf(mx, __shfl_xor_sync(0xffffffffu, mx, off));
            float p0 = __expf(v0 - mx);
            float p1 = __expf(v1 - mx);
            float sum = p0 + p1;
            #pragma unroll
            for (int off = 16; off > 0; off >>= 1)
                sum += __shfl_xor_sync(0xffffffffu, sum, off);
            float inv = __fdividef(1.0f, sum);
            sWei[r * WS + lane]      = p0 * inv;
            sWei[r * WS + lane + 32] = p1 * inv;
        }
    }
    __syncthreads();

    // ---- Phase 4: out = wei @ V. 4 rows x 3 cols per thread.
    //      Per 4-s step: 4 LDS.128 (wei broadcast) + 12 scalar LDS (V) + 48 FMA.
    {
        float oacc[12];
        #pragma unroll
        for (int j = 0; j < 12; ++j) oacc[j] = 0.0f;

        #pragma unroll 2
        for (int s4 = 0; s4 < T_DIM; s4 += 4) {
            float4 w4[4];
            #pragma unroll
            for (int i = 0; i < 4; ++i)
                w4[i] = *(const float4*)&sWei[(t0 + i) * WS + s4];
            #pragma unroll
            for (int k = 0; k < 4; ++k) {
                float wv[4] = {
                    (&w4[0].x)[k], (&w4[1].x)[k], (&w4[2].x)[k], (&w4[3].x)[k]
                };
                #pragma unroll
                for (int j = 0; j < 3; ++j) {
                    float vv = sV[(s4 + k) * XS + h0 + j];
                    #pragma unroll
                    for (int i = 0; i < 4; ++i)
                        oacc[i * 3 + j] += wv[i] * vv;
                }
            }
        }
        float* op = out + b * (T_DIM * C_DIM);
        #pragma unroll
        for (int i = 0; i < 4; ++i)
            #pragma unroll
            for (int j = 0; j < 3; ++j)
                op[(t0 + i) * C_DIM + h0 + j] = oacc[i * 3 + j];
    }
}

extern "C" void kernel_launch(void* const* d_in, const int* in_sizes, int n_in,
                              void* d_out, int out_size)
{
    const float* x  = (const float*)d_in[0];
    const float* Wq = (const float*)d_in[1];
    const float* Wk = (const float*)d_in[2];
    const float* Wv = (const float*)d_in[3];
    float* out = (float*)d_out;

    const int B = in_sizes[0] / (T_DIM * C_DIM);   // 16384
    const size_t shmem = SMEM_FLOATS * sizeof(float);  // 69632 B

    cudaFuncSetAttribute(head_attn_kernel,
                         cudaFuncAttributeMaxDynamicSharedMemorySize, (int)shmem);

    head_attn_kernel<<<B, 256, shmem>>>(x, Wq, Wk, Wv, out);
}